// round 2
// baseline (speedup 1.0000x reference)
#include <cuda_runtime.h>

// NeighborhoodAttention 3D, NATTEN clamped window (3,7,7).
// Static shape: B=1, T=16, H=32, W=32, nh=8, D=128, fp32.
//
// Round 2: one warp handles a (1,2,2) query tile (4 queries), lanes split D
// (float4 each). Single pass over the 3x8x8 = 192-row key/value halo with
// online softmax. Each K/V row load feeds 4 queries -> 4x less L1 traffic
// per query and K,V loaded once (vs twice) -> ~6x crossbar reduction.
//
// Per key row:
//   - 4 partial dots per lane (16 FMA)
//   - folded multi-value reduce: 4 sums in 6 shuffles + 4 broadcasts
//   - per-query window mask (warp-uniform scalars)
//   - warp-uniform lazy max-rescale (rare branch), exp, PV accumulate (16 FMA)

#define T_  16
#define H_  32
#define W_  32
#define NH  8
#define DD  128
#define ROW4 (NH * DD / 4)          // 256 float4 per spatial location
#define SCALE 0.08838834764831845f  // 1/sqrt(128)
#define NEG_BIG  -1e30f
#define M_INIT   -1e9f

static __device__ __forceinline__ float dot4(float4 a, float4 b) {
    return a.x*b.x + a.y*b.y + a.z*b.z + a.w*b.w;
}

__global__ __launch_bounds__(256)
void na3d_tile122(const float* __restrict__ Q,
                  const float* __restrict__ K,
                  const float* __restrict__ V,
                  float* __restrict__ O)
{
    const int lane = threadIdx.x & 31;
    const int warp = threadIdx.x >> 5;
    const int wg   = blockIdx.x * 8 + warp;

    // 4096 tiles per head: t(16) x hh(16) x ww(16)
    const int head = wg >> 12;
    const int rem  = wg & 4095;
    const int t    = rem >> 8;
    const int h0   = ((rem >> 4) & 15) * 2;
    const int w0   = (rem & 15) * 2;

    const int st = min(max(t - 1, 0), T_ - 3);
    const int bh = min(max(h0 - 3, 0), H_ - 8);
    const int bw = min(max(w0 - 3, 0), W_ - 8);

    // per-query window starts (clamped)
    const int sh0 = min(max(h0 - 3, 0), H_ - 7);
    const int sh1 = min(max(h0 - 2, 0), H_ - 7);
    const int sw0 = min(max(w0 - 3, 0), W_ - 7);
    const int sw1 = min(max(w0 - 2, 0), W_ - 7);

    const float4* __restrict__ Q4 = (const float4*)Q;
    const float4* __restrict__ K4 = (const float4*)K;
    const float4* __restrict__ V4 = (const float4*)V;
    float4* __restrict__ O4 = (float4*)O;

    // query indices (q = dh*2 + dw)
    int qidx[4];
    qidx[0] = (t*1024 + (h0  )*32 + (w0  )) * ROW4 + head*32 + lane;
    qidx[1] = (t*1024 + (h0  )*32 + (w0+1)) * ROW4 + head*32 + lane;
    qidx[2] = (t*1024 + (h0+1)*32 + (w0  )) * ROW4 + head*32 + lane;
    qidx[3] = (t*1024 + (h0+1)*32 + (w0+1)) * ROW4 + head*32 + lane;

    float4 qv[4];
#pragma unroll
    for (int q = 0; q < 4; ++q) {
        float4 v = Q4[qidx[q]];
        v.x *= SCALE; v.y *= SCALE; v.z *= SCALE; v.w *= SCALE;
        qv[q] = v;
    }

    float4 acc0 = make_float4(0.f,0.f,0.f,0.f);
    float4 acc1 = make_float4(0.f,0.f,0.f,0.f);
    float4 acc2 = make_float4(0.f,0.f,0.f,0.f);
    float4 acc3 = make_float4(0.f,0.f,0.f,0.f);
    float m0 = M_INIT, m1 = M_INIT, m2 = M_INIT, m3 = M_INIT;
    float l0 = 0.f, l1 = 0.f, l2 = 0.f, l3 = 0.f;

    const bool loHalf = (lane < 16);

#pragma unroll
    for (int it = 0; it < 3; ++it) {
        const int kt = st + it;
#pragma unroll
        for (int ih = 0; ih < 8; ++ih) {
            const int kh = bh + ih;
            const bool vh0 = (kh >= sh0) && (kh < sh0 + 7);
            const bool vh1 = (kh >= sh1) && (kh < sh1 + 7);
            const int rowb = (kt*1024 + kh*32 + bw) * ROW4 + head*32 + lane;
#pragma unroll
            for (int iw = 0; iw < 8; ++iw) {
                const int kw = bw + iw;
                const bool vw0 = (kw >= sw0) && (kw < sw0 + 7);
                const bool vw1 = (kw >= sw1) && (kw < sw1 + 7);

                const float4 kk = K4[rowb + iw * ROW4];

                float d0 = dot4(qv[0], kk);
                float d1 = dot4(qv[1], kk);
                float d2 = dot4(qv[2], kk);
                float d3 = dot4(qv[3], kk);

                // folded 4-value warp reduce (6 shuffles):
                // stage1 xor16: lanes<16 keep q0,q1 ; lanes>=16 keep q2,q3
                float snd0 = loHalf ? d2 : d0;
                float w0r  = (loHalf ? d0 : d2) + __shfl_xor_sync(0xffffffffu, snd0, 16);
                float snd1 = loHalf ? d3 : d1;
                float w1r  = (loHalf ? d1 : d3) + __shfl_xor_sync(0xffffffffu, snd1, 16);
                // stage2 xor8: fold 2 -> 1
                const bool lo8 = (lane & 8) == 0;
                float snd2 = lo8 ? w1r : w0r;
                float u    = (lo8 ? w0r : w1r) + __shfl_xor_sync(0xffffffffu, snd2, 8);
                // finish within 8-lane group
                u += __shfl_xor_sync(0xffffffffu, u, 4);
                u += __shfl_xor_sync(0xffffffffu, u, 2);
                u += __shfl_xor_sync(0xffffffffu, u, 1);
                // lanes 0-7:q0  8-15:q1  16-23:q2  24-31:q3
                float s0 = __shfl_sync(0xffffffffu, u, 0);
                float s1 = __shfl_sync(0xffffffffu, u, 8);
                float s2 = __shfl_sync(0xffffffffu, u, 16);
                float s3 = __shfl_sync(0xffffffffu, u, 24);

                s0 = (vh0 && vw0) ? s0 : NEG_BIG;
                s1 = (vh0 && vw1) ? s1 : NEG_BIG;
                s2 = (vh1 && vw0) ? s2 : NEG_BIG;
                s3 = (vh1 && vw1) ? s3 : NEG_BIG;

                // warp-uniform lazy rescale (scores are lane-uniform)
                if ((s0 > m0) | (s1 > m1) | (s2 > m2) | (s3 > m3)) {
                    float n0 = fmaxf(m0, s0), c0 = __expf(m0 - n0);
                    float n1 = fmaxf(m1, s1), c1 = __expf(m1 - n1);
                    float n2 = fmaxf(m2, s2), c2 = __expf(m2 - n2);
                    float n3 = fmaxf(m3, s3), c3 = __expf(m3 - n3);
                    m0 = n0; m1 = n1; m2 = n2; m3 = n3;
                    l0 *= c0; l1 *= c1; l2 *= c2; l3 *= c3;
                    acc0.x *= c0; acc0.y *= c0; acc0.z *= c0; acc0.w *= c0;
                    acc1.x *= c1; acc1.y *= c1; acc1.z *= c1; acc1.w *= c1;
                    acc2.x *= c2; acc2.y *= c2; acc2.z *= c2; acc2.w *= c2;
                    acc3.x *= c3; acc3.y *= c3; acc3.z *= c3; acc3.w *= c3;
                }

                const float p0 = __expf(s0 - m0);
                const float p1 = __expf(s1 - m1);
                const float p2 = __expf(s2 - m2);
                const float p3 = __expf(s3 - m3);

                const float4 vv = V4[rowb + iw * ROW4];

                l0 += p0; l1 += p1; l2 += p2; l3 += p3;
                acc0.x = fmaf(p0, vv.x, acc0.x); acc0.y = fmaf(p0, vv.y, acc0.y);
                acc0.z = fmaf(p0, vv.z, acc0.z); acc0.w = fmaf(p0, vv.w, acc0.w);
                acc1.x = fmaf(p1, vv.x, acc1.x); acc1.y = fmaf(p1, vv.y, acc1.y);
                acc1.z = fmaf(p1, vv.z, acc1.z); acc1.w = fmaf(p1, vv.w, acc1.w);
                acc2.x = fmaf(p2, vv.x, acc2.x); acc2.y = fmaf(p2, vv.y, acc2.y);
                acc2.z = fmaf(p2, vv.z, acc2.z); acc2.w = fmaf(p2, vv.w, acc2.w);
                acc3.x = fmaf(p3, vv.x, acc3.x); acc3.y = fmaf(p3, vv.y, acc3.y);
                acc3.z = fmaf(p3, vv.z, acc3.z); acc3.w = fmaf(p3, vv.w, acc3.w);
            }
        }
    }

    const float i0 = 1.0f / l0;
    const float i1 = 1.0f / l1;
    const float i2 = 1.0f / l2;
    const float i3 = 1.0f / l3;
    acc0.x *= i0; acc0.y *= i0; acc0.z *= i0; acc0.w *= i0;
    acc1.x *= i1; acc1.y *= i1; acc1.z *= i1; acc1.w *= i1;
    acc2.x *= i2; acc2.y *= i2; acc2.z *= i2; acc2.w *= i2;
    acc3.x *= i3; acc3.y *= i3; acc3.z *= i3; acc3.w *= i3;

    O4[qidx[0]] = acc0;
    O4[qidx[1]] = acc1;
    O4[qidx[2]] = acc2;
    O4[qidx[3]] = acc3;
}

extern "C" void kernel_launch(void* const* d_in, const int* in_sizes, int n_in,
                              void* d_out, int out_size)
{
    const float* q = (const float*)d_in[0];
    const float* k = (const float*)d_in[1];
    const float* v = (const float*)d_in[2];
    float* out = (float*)d_out;

    // tiles: 8 heads * 16 t * 16 hh * 16 ww = 32768 warps, 8 warps/CTA
    const int blocks = 32768 / 8;   // 4096
    na3d_tile122<<<blocks, 256>>>(q, k, v, out);
}

// round 3
// speedup vs baseline: 1.2338x; 1.2338x over previous
#include <cuda_runtime.h>

// NeighborhoodAttention 3D, NATTEN clamped window (3,7,7).
// Static shape: B=1, T=16, H=32, W=32, nh=8, D=128, fp32.
//
// Round 3: one warp handles a (1,2,2) query tile (4 queries), lanes split D
// (float4/lane). TWO-PASS (no online softmax -> no serial dependency chain):
//   Pass 1: 3x8x8=192 halo key rows -> 4 dots/key, folded 6-shuffle reduce,
//           mask, store raw scores to smem[192][4]; per-lane max chain.
//   Mid:    warp-local exp + per-query sum (lane handles q = lane&3 slices).
//   Pass 2: PV; p0..p3 via one broadcast LDS.128 per key.
// Each K/V row amortized over 4 queries; all key iterations independent.

#define T_  16
#define H_  32
#define W_  32
#define NH  8
#define DD  128
#define ROW4 (NH * DD / 4)          // 256 float4 per spatial location
#define SCALE 0.08838834764831845f  // 1/sqrt(128)
#define NEG_BIG -1e30f
#define NKH 192                     // 3*8*8 halo rows

static __device__ __forceinline__ float dot4(float4 a, float4 b) {
    return a.x*b.x + a.y*b.y + a.z*b.z + a.w*b.w;
}

__global__ __launch_bounds__(256)
void na3d_t122_2p(const float* __restrict__ Q,
                  const float* __restrict__ K,
                  const float* __restrict__ V,
                  float* __restrict__ O)
{
    __shared__ float s_p[8][NKH][4];   // 24 KB: raw scores then probs

    const int lane = threadIdx.x & 31;
    const int warp = threadIdx.x >> 5;
    const int wg   = blockIdx.x * 8 + warp;

    // 4096 tiles per head: t(16) x hh(16) x ww(16)
    const int head = wg >> 12;
    const int rem  = wg & 4095;
    const int t    = rem >> 8;
    const int h0   = ((rem >> 4) & 15) * 2;
    const int w0   = (rem & 15) * 2;

    const int st = min(max(t - 1, 0), T_ - 3);
    const int bh = min(max(h0 - 3, 0), H_ - 8);
    const int bw = min(max(w0 - 3, 0), W_ - 8);

    const int sh0 = min(max(h0 - 3, 0), H_ - 7);
    const int sh1 = min(max(h0 - 2, 0), H_ - 7);
    const int sw0 = min(max(w0 - 3, 0), W_ - 7);
    const int sw1 = min(max(w0 - 2, 0), W_ - 7);

    const float4* __restrict__ Q4 = (const float4*)Q;
    const float4* __restrict__ K4 = (const float4*)K;
    const float4* __restrict__ V4 = (const float4*)V;
    float4* __restrict__ O4 = (float4*)O;

    int qidx[4];
    qidx[0] = (t*1024 + (h0  )*32 + (w0  )) * ROW4 + head*32 + lane;
    qidx[1] = (t*1024 + (h0  )*32 + (w0+1)) * ROW4 + head*32 + lane;
    qidx[2] = (t*1024 + (h0+1)*32 + (w0  )) * ROW4 + head*32 + lane;
    qidx[3] = (t*1024 + (h0+1)*32 + (w0+1)) * ROW4 + head*32 + lane;

    float4 qv[4];
#pragma unroll
    for (int q = 0; q < 4; ++q) {
        float4 x = Q4[qidx[q]];
        x.x *= SCALE; x.y *= SCALE; x.z *= SCALE; x.w *= SCALE;
        qv[q] = x;
    }

    const bool loHalf = (lane < 16);
    const bool lo8    = (lane & 8) == 0;
    const int  grp    = lane >> 3;          // 0..3 -> which query this lane's sum is
    float* sp = &s_p[warp][0][0];

    // group validity lookup inputs (computed per ih/iw below)
    float m = NEG_BIG;                      // per-lane running max of its group's scores

    // ---------------- Pass 1: scores ----------------
    int kidx = 0;
#pragma unroll
    for (int it = 0; it < 3; ++it) {
        const int kt = st + it;
#pragma unroll
        for (int ih = 0; ih < 8; ++ih) {
            const int kh = bh + ih;
            const bool vh0 = (kh >= sh0) && (kh < sh0 + 7);
            const bool vh1 = (kh >= sh1) && (kh < sh1 + 7);
            const int rowb = (kt*1024 + kh*32 + bw) * ROW4 + head*32 + lane;
#pragma unroll
            for (int iw = 0; iw < 8; ++iw) {
                const int kw = bw + iw;
                const bool vw0 = (kw >= sw0) && (kw < sw0 + 7);
                const bool vw1 = (kw >= sw1) && (kw < sw1 + 7);

                const float4 kk = K4[rowb + iw * ROW4];

                float d0 = dot4(qv[0], kk);
                float d1 = dot4(qv[1], kk);
                float d2 = dot4(qv[2], kk);
                float d3 = dot4(qv[3], kk);

                // fold 4 -> 1 while reducing lanes (6 shuffles total):
                float snd0 = loHalf ? d2 : d0;
                float w0r  = (loHalf ? d0 : d2) + __shfl_xor_sync(0xffffffffu, snd0, 16);
                float snd1 = loHalf ? d3 : d1;
                float w1r  = (loHalf ? d1 : d3) + __shfl_xor_sync(0xffffffffu, snd1, 16);
                float snd2 = lo8 ? w1r : w0r;
                float u    = (lo8 ? w0r : w1r) + __shfl_xor_sync(0xffffffffu, snd2, 8);
                u += __shfl_xor_sync(0xffffffffu, u, 4);
                u += __shfl_xor_sync(0xffffffffu, u, 2);
                u += __shfl_xor_sync(0xffffffffu, u, 1);
                // lanes 0-7 hold s(q0), 8-15 s(q1), 16-23 s(q2), 24-31 s(q3)

                // per-lane mask for its group
                const bool vh = (grp < 2) ? vh0 : vh1;
                const bool vw = ((grp & 1) == 0) ? vw0 : vw1;
                const float s = (vh && vw) ? u : NEG_BIG;

                m = fmaxf(m, s);                       // independent chain
                if ((lane & 7) == 0)                   // lanes 0,8,16,24
                    sp[kidx * 4 + grp] = s;            // 16B contiguous -> 1 wf
                ++kidx;
            }
        }
    }
    __syncwarp();

    // ---------------- Mid: exp + sums ----------------
    // lane's exp slice touches only q = lane&3 (since 192*4 flat, stride 32)
    const float myM = __shfl_sync(0xffffffffu, m, (lane & 3) * 8);
    float sum = 0.0f;
#pragma unroll
    for (int i = 0; i < (NKH * 4) / 32; ++i) {         // 24 iters
        const int idx = i * 32 + lane;
        const float p = __expf(sp[idx] - myM);
        sp[idx] = p;
        sum += p;
    }
    // reduce across lanes sharing (lane&3)
    sum += __shfl_xor_sync(0xffffffffu, sum, 4);
    sum += __shfl_xor_sync(0xffffffffu, sum, 8);
    sum += __shfl_xor_sync(0xffffffffu, sum, 16);
    const float inv = 1.0f / sum;                       // inv for q = lane&3
    const float i0 = __shfl_sync(0xffffffffu, inv, 0);
    const float i1 = __shfl_sync(0xffffffffu, inv, 1);
    const float i2 = __shfl_sync(0xffffffffu, inv, 2);
    const float i3 = __shfl_sync(0xffffffffu, inv, 3);
    __syncwarp();

    // ---------------- Pass 2: PV ----------------
    float4 acc0 = make_float4(0.f,0.f,0.f,0.f);
    float4 acc1 = make_float4(0.f,0.f,0.f,0.f);
    float4 acc2 = make_float4(0.f,0.f,0.f,0.f);
    float4 acc3 = make_float4(0.f,0.f,0.f,0.f);

    kidx = 0;
#pragma unroll
    for (int it = 0; it < 3; ++it) {
        const int kt = st + it;
#pragma unroll
        for (int ih = 0; ih < 8; ++ih) {
            const int kh = bh + ih;
            const int rowb = (kt*1024 + kh*32 + bw) * ROW4 + head*32 + lane;
#pragma unroll
            for (int iw = 0; iw < 8; ++iw) {
                const float4 pq = *(const float4*)&sp[kidx * 4];  // broadcast
                const float4 vv = V4[rowb + iw * ROW4];
                acc0.x = fmaf(pq.x, vv.x, acc0.x); acc0.y = fmaf(pq.x, vv.y, acc0.y);
                acc0.z = fmaf(pq.x, vv.z, acc0.z); acc0.w = fmaf(pq.x, vv.w, acc0.w);
                acc1.x = fmaf(pq.y, vv.x, acc1.x); acc1.y = fmaf(pq.y, vv.y, acc1.y);
                acc1.z = fmaf(pq.y, vv.z, acc1.z); acc1.w = fmaf(pq.y, vv.w, acc1.w);
                acc2.x = fmaf(pq.z, vv.x, acc2.x); acc2.y = fmaf(pq.z, vv.y, acc2.y);
                acc2.z = fmaf(pq.z, vv.z, acc2.z); acc2.w = fmaf(pq.z, vv.w, acc2.w);
                acc3.x = fmaf(pq.w, vv.x, acc3.x); acc3.y = fmaf(pq.w, vv.y, acc3.y);
                acc3.z = fmaf(pq.w, vv.z, acc3.z); acc3.w = fmaf(pq.w, vv.w, acc3.w);
                ++kidx;
            }
        }
    }

    acc0.x *= i0; acc0.y *= i0; acc0.z *= i0; acc0.w *= i0;
    acc1.x *= i1; acc1.y *= i1; acc1.z *= i1; acc1.w *= i1;
    acc2.x *= i2; acc2.y *= i2; acc2.z *= i2; acc2.w *= i2;
    acc3.x *= i3; acc3.y *= i3; acc3.z *= i3; acc3.w *= i3;

    O4[qidx[0]] = acc0;
    O4[qidx[1]] = acc1;
    O4[qidx[2]] = acc2;
    O4[qidx[3]] = acc3;
}

extern "C" void kernel_launch(void* const* d_in, const int* in_sizes, int n_in,
                              void* d_out, int out_size)
{
    const float* q = (const float*)d_in[0];
    const float* k = (const float*)d_in[1];
    const float* v = (const float*)d_in[2];
    float* out = (float*)d_out;

    // 8 heads * 16 * 16 * 16 = 32768 warps, 8 warps/CTA
    const int blocks = 32768 / 8;   // 4096
    na3d_t122_2p<<<blocks, 256>>>(q, k, v, out);
}

// round 4
// speedup vs baseline: 2.5948x; 2.1031x over previous
#include <cuda_runtime.h>

// NeighborhoodAttention 3D, NATTEN clamped window (3,7,7).
// Static shape: B=1, T=16, H=32, W=32, nh=8, D=128, fp32.
//
// Round 4: R3 algorithm (warp = (1,2,2) query tile, two-pass over the
// 3x8x8=192-row K/V halo, smem score buffer) with BOUNDED UNROLLING:
// outer it/ih loops kept rolled (#pragma unroll 1), only iw=8 unrolled.
// This caps live registers (~64-70) -> 4 CTAs/SM instead of R3's regs=215,
// occ=12.5% register blowup.

#define T_  16
#define H_  32
#define W_  32
#define NH  8
#define DD  128
#define ROW4 (NH * DD / 4)          // 256 float4 per spatial location
#define SCALE 0.08838834764831845f  // 1/sqrt(128)
#define NEG_BIG -1e30f
#define NKH 192                     // 3*8*8 halo rows

static __device__ __forceinline__ float dot4(float4 a, float4 b) {
    return a.x*b.x + a.y*b.y + a.z*b.z + a.w*b.w;
}

__global__ __launch_bounds__(256)
void na3d_t122_2p_r4(const float* __restrict__ Q,
                     const float* __restrict__ K,
                     const float* __restrict__ V,
                     float* __restrict__ O)
{
    __shared__ float s_p[8][NKH][4];   // 24 KB: raw scores then probs

    const int lane = threadIdx.x & 31;
    const int warp = threadIdx.x >> 5;
    const int wg   = blockIdx.x * 8 + warp;

    // 4096 tiles per head: t(16) x hh(16) x ww(16)
    const int head = wg >> 12;
    const int rem  = wg & 4095;
    const int t    = rem >> 8;
    const int h0   = ((rem >> 4) & 15) * 2;
    const int w0   = (rem & 15) * 2;

    const int st = min(max(t - 1, 0), T_ - 3);
    const int bh = min(max(h0 - 3, 0), H_ - 8);
    const int bw = min(max(w0 - 3, 0), W_ - 8);

    const int sh0 = min(max(h0 - 3, 0), H_ - 7);
    const int sh1 = min(max(h0 - 2, 0), H_ - 7);
    const int sw0 = min(max(w0 - 3, 0), W_ - 7);
    const int sw1 = min(max(w0 - 2, 0), W_ - 7);

    const float4* __restrict__ Q4 = (const float4*)Q;
    const float4* __restrict__ K4 = (const float4*)K;
    const float4* __restrict__ V4 = (const float4*)V;
    float4* __restrict__ O4 = (float4*)O;

    const int qbase = (t*1024 + h0*32 + w0) * ROW4 + head*32 + lane;

    float4 qv[4];
    {
        float4 x;
        x = Q4[qbase];                 // (h0,   w0)
        x.x*=SCALE; x.y*=SCALE; x.z*=SCALE; x.w*=SCALE; qv[0]=x;
        x = Q4[qbase + ROW4];          // (h0,   w0+1)
        x.x*=SCALE; x.y*=SCALE; x.z*=SCALE; x.w*=SCALE; qv[1]=x;
        x = Q4[qbase + 32*ROW4];       // (h0+1, w0)
        x.x*=SCALE; x.y*=SCALE; x.z*=SCALE; x.w*=SCALE; qv[2]=x;
        x = Q4[qbase + 33*ROW4];       // (h0+1, w0+1)
        x.x*=SCALE; x.y*=SCALE; x.z*=SCALE; x.w*=SCALE; qv[3]=x;
    }

    const bool loHalf = (lane < 16);
    const bool lo8    = (lane & 8) == 0;
    const int  grp    = lane >> 3;          // which query this lane's score is
    float* sp = &s_p[warp][0][0];

    // per-lane (per-group) w-validity, precomputed for the 8 halo columns
    unsigned wmask = 0;
    {
        const int swg = (grp & 1) ? sw1 : sw0;
        #pragma unroll
        for (int iw = 0; iw < 8; ++iw) {
            const int kw = bw + iw;
            if (kw >= swg && kw < swg + 7) wmask |= (1u << iw);
        }
    }
    const int shg = (grp < 2) ? sh0 : sh1;

    float m = NEG_BIG;

    // ---------------- Pass 1: scores ----------------
    const int kbase = (st*1024 + bh*32 + bw) * ROW4 + head*32 + lane;
    int kidx4 = 0;                      // kidx*4
    #pragma unroll 1
    for (int it = 0; it < 3; ++it) {
        #pragma unroll 1
        for (int ih = 0; ih < 8; ++ih) {
            const int kh = bh + ih;
            const bool vh = (kh >= shg) && (kh < shg + 7);
            const int rowb = kbase + (it*1024 + ih*32) * ROW4;
            #pragma unroll
            for (int iw = 0; iw < 8; ++iw) {
                const float4 kk = K4[rowb + iw * ROW4];

                float d0 = dot4(qv[0], kk);
                float d1 = dot4(qv[1], kk);
                float d2 = dot4(qv[2], kk);
                float d3 = dot4(qv[3], kk);

                // fold 4 values -> 1 while reducing lanes (6 shuffles):
                float snd0 = loHalf ? d2 : d0;
                float w0r  = (loHalf ? d0 : d2) + __shfl_xor_sync(0xffffffffu, snd0, 16);
                float snd1 = loHalf ? d3 : d1;
                float w1r  = (loHalf ? d1 : d3) + __shfl_xor_sync(0xffffffffu, snd1, 16);
                float snd2 = lo8 ? w1r : w0r;
                float u    = (lo8 ? w0r : w1r) + __shfl_xor_sync(0xffffffffu, snd2, 8);
                u += __shfl_xor_sync(0xffffffffu, u, 4);
                u += __shfl_xor_sync(0xffffffffu, u, 2);
                u += __shfl_xor_sync(0xffffffffu, u, 1);
                // lanes 0-7: s(q0), 8-15: s(q1), 16-23: s(q2), 24-31: s(q3)

                const bool ok = vh && ((wmask >> iw) & 1u);
                const float s = ok ? u : NEG_BIG;

                m = fmaxf(m, s);
                if ((lane & 7) == 0)
                    sp[kidx4 + iw*4 + grp] = s;
            }
            kidx4 += 32;               // 8 keys * 4
        }
    }
    __syncwarp();

    // ---------------- Mid: exp + per-query sums ----------------
    const float myM = __shfl_sync(0xffffffffu, m, (lane & 3) * 8);
    float sum = 0.0f;
    #pragma unroll
    for (int i = 0; i < (NKH * 4) / 32; ++i) {     // 24 iters, lane's q = lane&3
        const int idx = i * 32 + lane;
        const float p = __expf(sp[idx] - myM);
        sp[idx] = p;
        sum += p;
    }
    sum += __shfl_xor_sync(0xffffffffu, sum, 4);
    sum += __shfl_xor_sync(0xffffffffu, sum, 8);
    sum += __shfl_xor_sync(0xffffffffu, sum, 16);
    const float inv = 1.0f / sum;                   // for q = lane&3
    const float i0 = __shfl_sync(0xffffffffu, inv, 0);
    const float i1 = __shfl_sync(0xffffffffu, inv, 1);
    const float i2 = __shfl_sync(0xffffffffu, inv, 2);
    const float i3 = __shfl_sync(0xffffffffu, inv, 3);
    __syncwarp();

    // ---------------- Pass 2: PV ----------------
    float4 acc0 = make_float4(0.f,0.f,0.f,0.f);
    float4 acc1 = make_float4(0.f,0.f,0.f,0.f);
    float4 acc2 = make_float4(0.f,0.f,0.f,0.f);
    float4 acc3 = make_float4(0.f,0.f,0.f,0.f);

    kidx4 = 0;
    #pragma unroll 1
    for (int it = 0; it < 3; ++it) {
        #pragma unroll 1
        for (int ih = 0; ih < 8; ++ih) {
            const int rowb = kbase + (it*1024 + ih*32) * ROW4;
            #pragma unroll
            for (int iw = 0; iw < 8; ++iw) {
                const float4 pq = *(const float4*)&sp[kidx4 + iw*4];  // broadcast LDS.128
                const float4 vv = V4[rowb + iw * ROW4];
                acc0.x = fmaf(pq.x, vv.x, acc0.x); acc0.y = fmaf(pq.x, vv.y, acc0.y);
                acc0.z = fmaf(pq.x, vv.z, acc0.z); acc0.w = fmaf(pq.x, vv.w, acc0.w);
                acc1.x = fmaf(pq.y, vv.x, acc1.x); acc1.y = fmaf(pq.y, vv.y, acc1.y);
                acc1.z = fmaf(pq.y, vv.z, acc1.z); acc1.w = fmaf(pq.y, vv.w, acc1.w);
                acc2.x = fmaf(pq.z, vv.x, acc2.x); acc2.y = fmaf(pq.z, vv.y, acc2.y);
                acc2.z = fmaf(pq.z, vv.z, acc2.z); acc2.w = fmaf(pq.z, vv.w, acc2.w);
                acc3.x = fmaf(pq.w, vv.x, acc3.x); acc3.y = fmaf(pq.w, vv.y, acc3.y);
                acc3.z = fmaf(pq.w, vv.z, acc3.z); acc3.w = fmaf(pq.w, vv.w, acc3.w);
            }
            kidx4 += 32;
        }
    }

    acc0.x *= i0; acc0.y *= i0; acc0.z *= i0; acc0.w *= i0;
    acc1.x *= i1; acc1.y *= i1; acc1.z *= i1; acc1.w *= i1;
    acc2.x *= i2; acc2.y *= i2; acc2.z *= i2; acc2.w *= i2;
    acc3.x *= i3; acc3.y *= i3; acc3.z *= i3; acc3.w *= i3;

    O4[qbase]           = acc0;
    O4[qbase + ROW4]    = acc1;
    O4[qbase + 32*ROW4] = acc2;
    O4[qbase + 33*ROW4] = acc3;
}

extern "C" void kernel_launch(void* const* d_in, const int* in_sizes, int n_in,
                              void* d_out, int out_size)
{
    const float* q = (const float*)d_in[0];
    const float* k = (const float*)d_in[1];
    const float* v = (const float*)d_in[2];
    float* out = (float*)d_out;

    // 8 heads * 16 * 16 * 16 = 32768 warps, 8 warps/CTA
    const int blocks = 32768 / 8;   // 4096
    na3d_t122_2p_r4<<<blocks, 256>>>(q, k, v, out);
}